// round 15
// baseline (speedup 1.0000x reference)
#include <cuda_runtime.h>
#include <cuda_fp16.h>
#include <cstdint>
#include <cstdio>

#define BATCH 8
#define NPTS 8192
#define N1 8193
#define SPTS 1024
#define FEATC 64
#define CIN0 67
#define NS0 32
#define NS1 64
#define M0 (BATCH*SPTS*NS0)   /* 262144 */
#define M1 (BATCH*SPTS*NS1)   /* 524288 */
#define NWIN 8192             /* M0/NS0 == M1/NS1 */

// ---------------- static scratch (allocation is forbidden) ----------------
// Intermediates stored as fp16 (consumer re-rounds to tf32 anyway).
__device__ __half  d_bufA0[(size_t)64*M0];
__device__ __half  d_bufB0[(size_t)64*M0];
__device__ __half  d_bufA1[(size_t)64*M1];
__device__ __half  d_bufB1[(size_t)128*M1];
__device__ float   d_featT[(size_t)BATCH*NPTS*FEATC];
__device__ float   d_pmax[(size_t)384*NWIN];
__device__ float   d_pmin[(size_t)384*NWIN];
__device__ float   d_meanv[BATCH*3];
__device__ int     d_idx0[(size_t)BATCH*SPTS*NS0];
__device__ int     d_idx1[(size_t)BATCH*SPTS*NS1];
__device__ float   d_gsum[6*256];
__device__ float   d_gsq [6*256];
__device__ float   d_scl [6*256];
__device__ float   d_shf [6*256];

// ---------------- tf32 / f32x2 helpers ----------------
typedef unsigned long long u64;
__device__ __forceinline__ float tf32r(float x){
    unsigned u; asm("cvt.rna.tf32.f32 %0, %1;" : "=r"(u) : "f"(x));
    return __uint_as_float(u);
}
__device__ __forceinline__ void mma8(float* c, const float* a, const float* b){
    asm volatile("mma.sync.aligned.m16n8k8.row.col.f32.tf32.tf32.f32 "
      "{%0,%1,%2,%3},{%4,%5,%6,%7},{%8,%9},{%0,%1,%2,%3};"
      : "+f"(c[0]),"+f"(c[1]),"+f"(c[2]),"+f"(c[3])
      : "r"(__float_as_uint(a[0])),"r"(__float_as_uint(a[1])),
        "r"(__float_as_uint(a[2])),"r"(__float_as_uint(a[3])),
        "r"(__float_as_uint(b[0])),"r"(__float_as_uint(b[1])));
}
__device__ __forceinline__ u64 pk2(float x, float y){
    u64 r; asm("mov.b64 %0, {%1,%2};" : "=l"(r) : "f"(x), "f"(y)); return r;
}
#define ADD2(d,a,b) asm("add.rn.f32x2 %0, %1, %2;" : "=l"(d) : "l"(a), "l"(b))
#define MUL2(d,a,b) asm("mul.rn.f32x2 %0, %1, %2;" : "=l"(d) : "l"(a), "l"(b))
#define UNPK2(lo,hi,v) asm("mov.b64 {%0,%1}, %2;" : "=f"(lo), "=f"(hi) : "l"(v))

// ---------------- zero stats ----------------
__global__ void zero_stats_kernel(float* gsum, float* gsq){
    int i = blockIdx.x*blockDim.x + threadIdx.x;
    if(i < 6*256){ gsum[i]=0.f; gsq[i]=0.f; }
}

// ---------------- mean over points ----------------
__global__ void mean_kernel(const float* __restrict__ xyz, float* __restrict__ meanv){
    int b = blockIdx.x, t = threadIdx.x;
    double sx=0, sy=0, sz=0;
    for(int n=t; n<NPTS; n+=256){
        const float* p = xyz + ((size_t)b*NPTS + n)*3;
        sx += (double)p[0]; sy += (double)p[1]; sz += (double)p[2];
    }
    __shared__ double rx[256], ry[256], rz[256];
    rx[t]=sx; ry[t]=sy; rz[t]=sz; __syncthreads();
    for(int o=128;o;o>>=1){
        if(t<o){ rx[t]+=rx[t+o]; ry[t]+=ry[t+o]; rz[t]+=rz[t+o]; }
        __syncthreads();
    }
    if(t==0){
        meanv[b*3+0]=(float)(rx[0]/NPTS);
        meanv[b*3+1]=(float)(ry[0]/NPTS);
        meanv[b*3+2]=(float)(rz[0]/NPTS);
    }
}

// ---------------- farthest point sampling (as R11) ----------------
__global__ __launch_bounds__(1024) void fps_kernel(const float* __restrict__ xyz,
                                                   const float* __restrict__ meanv,
                                                   float* __restrict__ newxyz){
    extern __shared__ float sh[];          // sx[N1], sy[N1], sz[N1]
    float* sx = sh;
    float* sy = sh + N1;
    float* sz = sh + 2*N1;
    __shared__ unsigned swv[2][32]; __shared__ int swi[2][32];
    int b = blockIdx.x, t = threadIdx.x;
    int lane = t & 31, wrp = t >> 5;

    for(int i=t; i<N1; i+=1024){
        if(i==0){ sx[0]=meanv[b*3]; sy[0]=meanv[b*3+1]; sz[0]=meanv[b*3+2]; }
        else{
            const float* p = xyz + ((size_t)b*NPTS + (i-1))*3;
            sx[i]=p[0]; sy[i]=p[1]; sz[i]=p[2];
        }
    }
    __syncthreads();

    u64 pxp[4], pyp[4], pzp[4];
    float dist[8];
    #pragma unroll
    for(int q=0;q<4;q++){
        int i0 = t + (2*q)*1024, i1 = t + (2*q+1)*1024;
        pxp[q] = pk2(sx[i0], sx[i1]);
        pyp[q] = pk2(sy[i0], sy[i1]);
        pzp[q] = pk2(sz[i0], sz[i1]);
        dist[2*q] = 1e10f; dist[2*q+1] = 1e10f;
    }
    float px8=0.f, py8=0.f, pz8=0.f, dist8=1e10f;
    if(t==0){ px8=sx[8192]; py8=sy[8192]; pz8=sz[8192]; }

    float cx = sx[0], cy = sy[0], cz = sz[0];
    int par = 0;
    for(int s=0;s<SPTS;s++){
        if(t==0){
            float* o = newxyz + ((size_t)b*SPTS + s)*3;
            o[0]=cx; o[1]=cy; o[2]=cz;
        }
        float ncx = -cx, ncy = -cy, ncz = -cz;
        u64 cxp = pk2(ncx,ncx), cyp = pk2(ncy,ncy), czp = pk2(ncz,ncz);
        float bv = -2.0f; int bi = 0;
        #pragma unroll
        for(int q=0;q<4;q++){
            u64 dx, dy, dz, xx, yy, zz, s1, dd;
            ADD2(dx, pxp[q], cxp);
            ADD2(dy, pyp[q], cyp);
            ADD2(dz, pzp[q], czp);
            MUL2(xx, dx, dx);
            MUL2(yy, dy, dy);
            MUL2(zz, dz, dz);
            ADD2(s1, xx, yy);
            ADD2(dd, s1, zz);
            float d0, d1; UNPK2(d0, d1, dd);
            float nd0 = fminf(dist[2*q], d0);   dist[2*q] = nd0;
            if(nd0 > bv){ bv = nd0; bi = t + (2*q)*1024; }
            float nd1 = fminf(dist[2*q+1], d1); dist[2*q+1] = nd1;
            if(nd1 > bv){ bv = nd1; bi = t + (2*q+1)*1024; }
        }
        if(t==0){
            float dx = __fadd_rn(px8, ncx);
            float dy = __fadd_rn(py8, ncy);
            float dz = __fadd_rn(pz8, ncz);
            float d  = __fadd_rn(__fadd_rn(__fmul_rn(dx,dx), __fmul_rn(dy,dy)), __fmul_rn(dz,dz));
            float nd = fminf(dist8, d); dist8 = nd;
            if(nd > bv){ bv = nd; bi = 8192; }
        }
        unsigned u = __float_as_uint(bv);
        unsigned m = __reduce_max_sync(0xffffffffu, u);
        int cand = (u == m) ? bi : 0x7fffffff;
        int wmin = __reduce_min_sync(0xffffffffu, cand);
        if(lane == 0){ swv[par][wrp] = m; swi[par][wrp] = wmin; }
        __syncthreads();
        unsigned u2 = swv[par][lane]; int j2 = swi[par][lane];
        unsigned m2 = __reduce_max_sync(0xffffffffu, u2);
        int cand2 = (u2 == m2) ? j2 : 0x7fffffff;
        int far = __reduce_min_sync(0xffffffffu, cand2);
        cx = sx[far]; cy = sy[far]; cz = sz[far];
        par ^= 1;
    }
}

// ---------------- feature transpose (B,C,N) -> (B,N,C) ----------------
__global__ void transpose_kernel(const float* __restrict__ f, float* __restrict__ ft){
    __shared__ float tile[32][33];
    int b = blockIdx.z;
    int n0 = blockIdx.x*32, c0 = blockIdx.y*32;
    int tx = threadIdx.x, ty = threadIdx.y;
    #pragma unroll
    for(int i=0;i<32;i+=8)
        tile[ty+i][tx] = f[((size_t)b*FEATC + (c0+ty+i))*NPTS + n0 + tx];
    __syncthreads();
    #pragma unroll
    for(int i=0;i<32;i+=8)
        ft[((size_t)b*NPTS + (n0+ty+i))*FEATC + c0 + tx] = tile[tx][ty+i];
}

// ---------------- ball query (both radii in one pass) ----------------
__global__ __launch_bounds__(256) void ballq_kernel(const float* __restrict__ xyz,
                                                    const float* __restrict__ nx,
                                                    int* __restrict__ idx0,
                                                    int* __restrict__ idx1){
    int gw = (blockIdx.x*blockDim.x + threadIdx.x) >> 5;
    int lane = threadIdx.x & 31;
    int b = gw >> 10, s = gw & 1023;
    const float R20 = (float)(0.4*0.4);
    const float R21 = (float)(0.8*0.8);
    const float* cp = nx + ((size_t)b*SPTS + s)*3;
    float cx=cp[0], cy=cp[1], cz=cp[2];
    int cnt0=0, cnt1=0, first0=0, first1=0;
    size_t base0 = ((size_t)b*SPTS + s)*NS0;
    size_t base1 = ((size_t)b*SPTS + s)*NS1;
    unsigned lmask = (1u << lane) - 1u;
    for(int ch=0; ch<NPTS/32; ch++){
        if(cnt0 >= NS0 && cnt1 >= NS1) break;
        int n = ch*32 + lane;
        const float* p = xyz + ((size_t)b*NPTS + n)*3;
        float dx = __fadd_rn(cx, -p[0]);
        float dy = __fadd_rn(cy, -p[1]);
        float dz = __fadd_rn(cz, -p[2]);
        float d2 = __fadd_rn(__fadd_rn(__fmul_rn(dx,dx), __fmul_rn(dy,dy)), __fmul_rn(dz,dz));
        unsigned m1 = __ballot_sync(0xffffffffu, d2 < R21);
        unsigned m0 = __ballot_sync(0xffffffffu, d2 < R20);
        if(m0 && cnt0 < NS0){
            if(cnt0 == 0) first0 = ch*32 + __ffs(m0) - 1;
            if((m0 >> lane) & 1){
                int r = __popc(m0 & lmask);
                if(cnt0 + r < NS0) idx0[base0 + cnt0 + r] = n;
            }
            cnt0 = min(NS0, cnt0 + __popc(m0));
        }
        if(m1 && cnt1 < NS1){
            if(cnt1 == 0) first1 = ch*32 + __ffs(m1) - 1;
            if((m1 >> lane) & 1){
                int r = __popc(m1 & lmask);
                if(cnt1 + r < NS1) idx1[base1 + cnt1 + r] = n;
            }
            cnt1 = min(NS1, cnt1 + __popc(m1));
        }
    }
    int p0 = (cnt0 > 0) ? first0 : 0;
    for(int k=cnt0+lane; k<NS0; k+=32) idx0[base0+k] = p0;
    int p1 = (cnt1 > 0) ? first1 : 0;
    for(int k=cnt1+lane; k<NS1; k+=32) idx1[base1+k] = p1;
}

// ==================================================================
// Fused gather + tensor-core GEMM (layer 0). Y stored as fp16.
// ==================================================================
#define GX_STRIDE 264
#define GX_ROWS   80
#define G_SMEM    ((GX_ROWS*GX_STRIDE + 64*20)*4)

__global__ __launch_bounds__(256) void gemm_g_kernel(const float* __restrict__ W,
        const float* __restrict__ xyz, const float* __restrict__ ft,
        const float* __restrict__ nx, const int* __restrict__ idx,
        __half* __restrict__ Y, int M, int ns,
        float* __restrict__ gsum, float* __restrict__ gsq){
    extern __shared__ float dsm[];
    float* Xs = dsm;                       // [80][264]
    float* Wc = dsm + GX_ROWS*GX_STRIDE;   // [64][20]
    __shared__ float ssum[64], ssq[64];
    int tid = threadIdx.x;
    int lane = tid & 31, wn = tid >> 5;
    int g = lane >> 2, tg = lane & 3;
    int m0 = blockIdx.y * 256;
    if(tid < 64){ ssum[tid]=0.f; ssq[tid]=0.f; }

    // prefetch W chunk 0
    float wreg[4];
    #pragma unroll
    for(int i=0;i<4;i++){
        int ix = tid + i*256;
        int o = ix >> 4, k = ix & 15;
        wreg[i] = (k < CIN0) ? W[(size_t)o*CIN0 + k] : 0.f;
    }

    {
        int m = m0 + tid;
        int sc_ = m / ns;
        int s = sc_ & 1023, b = sc_ >> 10;
        int id = idx[m];
        const float* p = xyz + ((size_t)b*NPTS + id)*3;
        const float* c = nx  + ((size_t)b*SPTS + s)*3;
        Xs[0*GX_STRIDE + tid] = tf32r(p[0]-c[0]);
        Xs[1*GX_STRIDE + tid] = tf32r(p[1]-c[1]);
        Xs[2*GX_STRIDE + tid] = tf32r(p[2]-c[2]);
        const float4* fr = (const float4*)(ft + ((size_t)b*NPTS + id)*FEATC);
        #pragma unroll
        for(int j=0;j<16;j++){
            float4 v = fr[j];
            Xs[(3+4*j+0)*GX_STRIDE + tid] = tf32r(v.x);
            Xs[(3+4*j+1)*GX_STRIDE + tid] = tf32r(v.y);
            Xs[(3+4*j+2)*GX_STRIDE + tid] = tf32r(v.z);
            Xs[(3+4*j+3)*GX_STRIDE + tid] = tf32r(v.w);
        }
        #pragma unroll
        for(int k=CIN0;k<GX_ROWS;k++) Xs[k*GX_STRIDE + tid] = 0.f;
    }

    float acc[4][4][4];
    #pragma unroll
    for(int mt=0;mt<4;mt++)
        #pragma unroll
        for(int nt=0;nt<4;nt++)
            #pragma unroll
            for(int i=0;i<4;i++) acc[mt][nt][i]=0.f;
    __syncthreads();

    for(int kc=0; kc<5; kc++){
        int kb = kc*16;
        #pragma unroll
        for(int i=0;i<4;i++){
            int ix = tid + i*256;
            int o = ix >> 4, k = ix & 15;
            Wc[o*20 + k] = tf32r(wreg[i]);
        }
        __syncthreads();
        if(kc < 4){
            int kb2 = kb + 16;
            #pragma unroll
            for(int i=0;i<4;i++){
                int ix = tid + i*256;
                int o = ix >> 4, k = ix & 15;
                wreg[i] = (kb2 + k < CIN0) ? W[(size_t)o*CIN0 + kb2 + k] : 0.f;
            }
        }
        #pragma unroll
        for(int s8=0; s8<2; s8++){
            int ko = kb + s8*8, kl = s8*8;
            float a[4][4], b[4][2];
            #pragma unroll
            for(int mt=0;mt<4;mt++){
                int r0 = (mt*16 + g)*20 + kl + tg;
                a[mt][0] = Wc[r0];
                a[mt][1] = Wc[r0 + 160];
                a[mt][2] = Wc[r0 + 4];
                a[mt][3] = Wc[r0 + 164];
            }
            #pragma unroll
            for(int nt=0;nt<4;nt++){
                int cb = wn*32 + nt*8 + g;
                b[nt][0] = Xs[(ko+tg)*GX_STRIDE + cb];
                b[nt][1] = Xs[(ko+tg+4)*GX_STRIDE + cb];
            }
            #pragma unroll
            for(int mt=0;mt<4;mt++)
                #pragma unroll
                for(int nt=0;nt<4;nt++)
                    mma8(acc[mt][nt], a[mt], b[nt]);
        }
        __syncthreads();
    }

    float s8v[8], q8v[8];
    #pragma unroll
    for(int i=0;i<8;i++){ s8v[i]=0.f; q8v[i]=0.f; }
    #pragma unroll
    for(int mt=0;mt<4;mt++)
        #pragma unroll
        for(int nt=0;nt<4;nt++){
            float c0=acc[mt][nt][0], c1=acc[mt][nt][1];
            float c2=acc[mt][nt][2], c3=acc[mt][nt][3];
            s8v[mt*2+0] += c0+c1; q8v[mt*2+0] += c0*c0 + c1*c1;
            s8v[mt*2+1] += c2+c3; q8v[mt*2+1] += c2*c2 + c3*c3;
        }
    #pragma unroll
    for(int i=0;i<8;i++){
        s8v[i] += __shfl_xor_sync(0xffffffffu, s8v[i], 1);
        s8v[i] += __shfl_xor_sync(0xffffffffu, s8v[i], 2);
        q8v[i] += __shfl_xor_sync(0xffffffffu, q8v[i], 1);
        q8v[i] += __shfl_xor_sync(0xffffffffu, q8v[i], 2);
    }
    if(tg == 0){
        #pragma unroll
        for(int mt=0;mt<4;mt++){
            atomicAdd(&ssum[mt*16 + g],     s8v[mt*2+0]);
            atomicAdd(&ssq [mt*16 + g],     q8v[mt*2+0]);
            atomicAdd(&ssum[mt*16 + g + 8], s8v[mt*2+1]);
            atomicAdd(&ssq [mt*16 + g + 8], q8v[mt*2+1]);
        }
    }
    #pragma unroll
    for(int mt=0;mt<4;mt++)
        #pragma unroll
        for(int nt=0;nt<4;nt++){
            int m = m0 + wn*32 + nt*8 + 2*tg;
            int r0 = mt*16 + g;
            *(__half2*)(Y + (size_t)r0*M + m)     = __floats2half2_rn(acc[mt][nt][0], acc[mt][nt][1]);
            *(__half2*)(Y + (size_t)(r0+8)*M + m) = __floats2half2_rn(acc[mt][nt][2], acc[mt][nt][3]);
        }
    __syncthreads();
    if(tid < 64){
        atomicAdd(&gsum[tid], ssum[tid]);
        atomicAdd(&gsq [tid], ssq [tid]);
    }
}

// ==================================================================
// Middle-layer GEMM: fp16 in, fp16 out; double-buffered staging.
// ==================================================================
__global__ __launch_bounds__(256) void gemm_tc_kernel(const float* __restrict__ W,
        const __half* __restrict__ X, __half* __restrict__ Y,
        int Cin, int Cout, int M,
        const float* __restrict__ tsc, const float* __restrict__ tsh,
        float* __restrict__ gsum, float* __restrict__ gsq){
    __shared__ float Xs[16*264];
    __shared__ float Wc[64*20];
    __shared__ float ssum[64], ssq[64];
    int tid = threadIdx.x;
    int lane = tid & 31, wn = tid >> 5;
    int g = lane >> 2, tg = lane & 3;
    int ob = blockIdx.x * 64;
    int m0 = blockIdx.y * 256;
    int rr = tid >> 4, cb = (tid & 15)*16;
    if(tid < 64){ ssum[tid]=0.f; ssq[tid]=0.f; }

    float acc[4][4][4];
    #pragma unroll
    for(int mt=0;mt<4;mt++)
        #pragma unroll
        for(int nt=0;nt<4;nt++)
            #pragma unroll
            for(int i=0;i<4;i++) acc[mt][nt][i]=0.f;

    int kchunks = (Cin + 15) >> 4;

    // prefetch chunk 0 (16 halves = 2 x uint4)
    uint4 xreg[2]; float wreg[4];
    {
        int cin = rr;
        if(cin < Cin){
            const uint4* p = (const uint4*)(X + (size_t)cin*M + m0 + cb);
            xreg[0] = p[0]; xreg[1] = p[1];
        } else {
            xreg[0] = make_uint4(0,0,0,0); xreg[1] = make_uint4(0,0,0,0);
        }
        #pragma unroll
        for(int i=0;i<4;i++){
            int ix = tid + i*256;
            int o = ix >> 4, k = ix & 15;
            wreg[i] = (k < Cin) ? W[(size_t)(ob+o)*Cin + k] : 0.f;
        }
    }

    for(int kc=0; kc<kchunks; kc++){
        int kb = kc*16;
        // ---- store staged chunk to SMEM (h2f + BN + tf32r here) ----
        {
            int cin = kb + rr;
            float v[16];
            const __half2* hp = (const __half2*)xreg;
            #pragma unroll
            for(int j=0;j<8;j++){
                float2 f = __half22float2(hp[j]);
                v[2*j] = f.x; v[2*j+1] = f.y;
            }
            if(cin < Cin){
                float s_ = tsc[cin], h_ = tsh[cin];
                #pragma unroll
                for(int j=0;j<16;j++) v[j] = tf32r(fmaxf(0.f, fmaf(s_, v[j], h_)));
            }
            #pragma unroll
            for(int j=0;j<16;j++) Xs[rr*264 + cb + j] = v[j];
        }
        #pragma unroll
        for(int i=0;i<4;i++){
            int ix = tid + i*256;
            int o = ix >> 4, k = ix & 15;
            Wc[o*20 + k] = tf32r(wreg[i]);
        }
        __syncthreads();
        // ---- prefetch next chunk ----
        if(kc + 1 < kchunks){
            int kb2 = kb + 16;
            int cin = kb2 + rr;
            if(cin < Cin){
                const uint4* p = (const uint4*)(X + (size_t)cin*M + m0 + cb);
                xreg[0] = p[0]; xreg[1] = p[1];
            } else {
                xreg[0] = make_uint4(0,0,0,0); xreg[1] = make_uint4(0,0,0,0);
            }
            #pragma unroll
            for(int i=0;i<4;i++){
                int ix = tid + i*256;
                int o = ix >> 4, k = ix & 15;
                wreg[i] = (kb2 + k < Cin) ? W[(size_t)(ob+o)*Cin + kb2 + k] : 0.f;
            }
        }
        // ---- MMAs for current chunk ----
        #pragma unroll
        for(int s8=0; s8<2; s8++){
            int ko = s8*8;
            float a[4][4], b[4][2];
            #pragma unroll
            for(int mt=0;mt<4;mt++){
                int r0 = (mt*16 + g)*20 + ko + tg;
                a[mt][0] = Wc[r0];
                a[mt][1] = Wc[r0 + 160];
                a[mt][2] = Wc[r0 + 4];
                a[mt][3] = Wc[r0 + 164];
            }
            #pragma unroll
            for(int nt=0;nt<4;nt++){
                int cbw = wn*32 + nt*8 + g;
                b[nt][0] = Xs[(ko+tg)*264 + cbw];
                b[nt][1] = Xs[(ko+tg+4)*264 + cbw];
            }
            #pragma unroll
            for(int mt=0;mt<4;mt++)
                #pragma unroll
                for(int nt=0;nt<4;nt++)
                    mma8(acc[mt][nt], a[mt], b[nt]);
        }
        __syncthreads();
    }

    float s8v[8], q8v[8];
    #pragma unroll
    for(int i=0;i<8;i++){ s8v[i]=0.f; q8v[i]=0.f; }
    #pragma unroll
    for(int mt=0;mt<4;mt++)
        #pragma unroll
        for(int nt=0;nt<4;nt++){
            float c0=acc[mt][nt][0], c1=acc[mt][nt][1];
            float c2=acc[mt][nt][2], c3=acc[mt][nt][3];
            s8v[mt*2+0] += c0+c1; q8v[mt*2+0] += c0*c0 + c1*c1;
            s8v[mt*2+1] += c2+c3; q8v[mt*2+1] += c2*c2 + c3*c3;
        }
    #pragma unroll
    for(int i=0;i<8;i++){
        s8v[i] += __shfl_xor_sync(0xffffffffu, s8v[i], 1);
        s8v[i] += __shfl_xor_sync(0xffffffffu, s8v[i], 2);
        q8v[i] += __shfl_xor_sync(0xffffffffu, q8v[i], 1);
        q8v[i] += __shfl_xor_sync(0xffffffffu, q8v[i], 2);
    }
    if(tg == 0){
        #pragma unroll
        for(int mt=0;mt<4;mt++){
            atomicAdd(&ssum[mt*16 + g],     s8v[mt*2+0]);
            atomicAdd(&ssq [mt*16 + g],     q8v[mt*2+0]);
            atomicAdd(&ssum[mt*16 + g + 8], s8v[mt*2+1]);
            atomicAdd(&ssq [mt*16 + g + 8], q8v[mt*2+1]);
        }
    }
    #pragma unroll
    for(int mt=0;mt<4;mt++)
        #pragma unroll
        for(int nt=0;nt<4;nt++){
            int m = m0 + wn*32 + nt*8 + 2*tg;
            int r0 = ob + mt*16 + g;
            *(__half2*)(Y + (size_t)r0*M + m)     = __floats2half2_rn(acc[mt][nt][0], acc[mt][nt][1]);
            *(__half2*)(Y + (size_t)(r0+8)*M + m) = __floats2half2_rn(acc[mt][nt][2], acc[mt][nt][3]);
        }
    __syncthreads();
    if(tid < 64){
        atomicAdd(&gsum[ob + tid], ssum[tid]);
        atomicAdd(&gsq [ob + tid], ssq [tid]);
    }
}

// ==================================================================
// Last-layer GEMM: fp16 in; no Y store; stats + pooled raw max/min (fp32).
// ==================================================================
__global__ __launch_bounds__(256) void gemm_tc_pool_kernel(const float* __restrict__ W,
        const __half* __restrict__ X, int Cin, int Cout, int M, int ns,
        const float* __restrict__ tsc, const float* __restrict__ tsh,
        float* __restrict__ gsum, float* __restrict__ gsq,
        float* __restrict__ gpmax, float* __restrict__ gpmin){
    __shared__ float Xs[16*264];
    __shared__ float Wc[64*20];
    __shared__ float ssum[64], ssq[64];
    __shared__ float pmaxS[64][8], pminS[64][8];
    int tid = threadIdx.x;
    int lane = tid & 31, wn = tid >> 5;
    int g = lane >> 2, tg = lane & 3;
    int ob = blockIdx.x * 64;
    int m0 = blockIdx.y * 256;
    int rr = tid >> 4, cb = (tid & 15)*16;
    if(tid < 64){ ssum[tid]=0.f; ssq[tid]=0.f; }

    float acc[4][4][4];
    #pragma unroll
    for(int mt=0;mt<4;mt++)
        #pragma unroll
        for(int nt=0;nt<4;nt++)
            #pragma unroll
            for(int i=0;i<4;i++) acc[mt][nt][i]=0.f;

    int kchunks = (Cin + 15) >> 4;

    uint4 xreg[2]; float wreg[4];
    {
        int cin = rr;
        if(cin < Cin){
            const uint4* p = (const uint4*)(X + (size_t)cin*M + m0 + cb);
            xreg[0] = p[0]; xreg[1] = p[1];
        } else {
            xreg[0] = make_uint4(0,0,0,0); xreg[1] = make_uint4(0,0,0,0);
        }
        #pragma unroll
        for(int i=0;i<4;i++){
            int ix = tid + i*256;
            int o = ix >> 4, k = ix & 15;
            wreg[i] = (k < Cin) ? W[(size_t)(ob+o)*Cin + k] : 0.f;
        }
    }

    for(int kc=0; kc<kchunks; kc++){
        int kb = kc*16;
        {
            int cin = kb + rr;
            float v[16];
            const __half2* hp = (const __half2*)xreg;
            #pragma unroll
            for(int j=0;j<8;j++){
                float2 f = __half22float2(hp[j]);
                v[2*j] = f.x; v[2*j+1] = f.y;
            }
            if(cin < Cin){
                float s_ = tsc[cin], h_ = tsh[cin];
                #pragma unroll
                for(int j=0;j<16;j++) v[j] = tf32r(fmaxf(0.f, fmaf(s_, v[j], h_)));
            }
            #pragma unroll
            for(int j=0;j<16;j++) Xs[rr*264 + cb + j] = v[j];
        }
        #pragma unroll
        for(int i=0;i<4;i++){
            int ix = tid + i*256;
            int o = ix >> 4, k = ix & 15;
            Wc[o*20 + k] = tf32r(wreg[i]);
        }
        __syncthreads();
        if(kc + 1 < kchunks){
            int kb2 = kb + 16;
            int cin = kb2 + rr;
            if(cin < Cin){
                const uint4* p = (const uint4*)(X + (size_t)cin*M + m0 + cb);
                xreg[0] = p[0]; xreg[1] = p[1];
            } else {
                xreg[0] = make_uint4(0,0,0,0); xreg[1] = make_uint4(0,0,0,0);
            }
            #pragma unroll
            for(int i=0;i<4;i++){
                int ix = tid + i*256;
                int o = ix >> 4, k = ix & 15;
                wreg[i] = (kb2 + k < Cin) ? W[(size_t)(ob+o)*Cin + kb2 + k] : 0.f;
            }
        }
        #pragma unroll
        for(int s8=0; s8<2; s8++){
            int ko = s8*8;
            float a[4][4], b[4][2];
            #pragma unroll
            for(int mt=0;mt<4;mt++){
                int r0 = (mt*16 + g)*20 + ko + tg;
                a[mt][0] = Wc[r0];
                a[mt][1] = Wc[r0 + 160];
                a[mt][2] = Wc[r0 + 4];
                a[mt][3] = Wc[r0 + 164];
            }
            #pragma unroll
            for(int nt=0;nt<4;nt++){
                int cbw = wn*32 + nt*8 + g;
                b[nt][0] = Xs[(ko+tg)*264 + cbw];
                b[nt][1] = Xs[(ko+tg+4)*264 + cbw];
            }
            #pragma unroll
            for(int mt=0;mt<4;mt++)
                #pragma unroll
                for(int nt=0;nt<4;nt++)
                    mma8(acc[mt][nt], a[mt], b[nt]);
        }
        __syncthreads();
    }

    float s8v[8], q8v[8];
    #pragma unroll
    for(int i=0;i<8;i++){ s8v[i]=0.f; q8v[i]=0.f; }
    #pragma unroll
    for(int mt=0;mt<4;mt++)
        #pragma unroll
        for(int nt=0;nt<4;nt++){
            float c0=acc[mt][nt][0], c1=acc[mt][nt][1];
            float c2=acc[mt][nt][2], c3=acc[mt][nt][3];
            s8v[mt*2+0] += c0+c1; q8v[mt*2+0] += c0*c0 + c1*c1;
            s8v[mt*2+1] += c2+c3; q8v[mt*2+1] += c2*c2 + c3*c3;
        }
    #pragma unroll
    for(int i=0;i<8;i++){
        s8v[i] += __shfl_xor_sync(0xffffffffu, s8v[i], 1);
        s8v[i] += __shfl_xor_sync(0xffffffffu, s8v[i], 2);
        q8v[i] += __shfl_xor_sync(0xffffffffu, q8v[i], 1);
        q8v[i] += __shfl_xor_sync(0xffffffffu, q8v[i], 2);
    }
    if(tg == 0){
        #pragma unroll
        for(int mt=0;mt<4;mt++){
            atomicAdd(&ssum[mt*16 + g],     s8v[mt*2+0]);
            atomicAdd(&ssq [mt*16 + g],     q8v[mt*2+0]);
            atomicAdd(&ssum[mt*16 + g + 8], s8v[mt*2+1]);
            atomicAdd(&ssq [mt*16 + g + 8], q8v[mt*2+1]);
        }
    }

    #pragma unroll
    for(int mt=0;mt<4;mt++){
        float mxA=-3.4e38f, mnA=3.4e38f, mxB=-3.4e38f, mnB=3.4e38f;
        #pragma unroll
        for(int nt=0;nt<4;nt++){
            mxA = fmaxf(mxA, fmaxf(acc[mt][nt][0], acc[mt][nt][1]));
            mnA = fminf(mnA, fminf(acc[mt][nt][0], acc[mt][nt][1]));
            mxB = fmaxf(mxB, fmaxf(acc[mt][nt][2], acc[mt][nt][3]));
            mnB = fminf(mnB, fminf(acc[mt][nt][2], acc[mt][nt][3]));
        }
        #pragma unroll
        for(int o=1;o<=2;o<<=1){
            mxA = fmaxf(mxA, __shfl_xor_sync(0xffffffffu, mxA, o));
            mnA = fminf(mnA, __shfl_xor_sync(0xffffffffu, mnA, o));
            mxB = fmaxf(mxB, __shfl_xor_sync(0xffffffffu, mxB, o));
            mnB = fminf(mnB, __shfl_xor_sync(0xffffffffu, mnB, o));
        }
        if(tg == 0){
            pmaxS[mt*16 + g][wn] = mxA;   pminS[mt*16 + g][wn] = mnA;
            pmaxS[mt*16 + g + 8][wn] = mxB; pminS[mt*16 + g + 8][wn] = mnB;
        }
    }
    __syncthreads();
    int nwin = 256/ns;
    int gsz  = ns/32;
    for(int i=tid; i<64*nwin; i+=256){
        int row = i / nwin, win = i % nwin;
        float mx=-3.4e38f, mn=3.4e38f;
        for(int j=0;j<gsz;j++){
            mx = fmaxf(mx, pmaxS[row][win*gsz + j]);
            mn = fminf(mn, pminS[row][win*gsz + j]);
        }
        size_t o = (size_t)(ob + row)*NWIN + m0/ns + win;
        gpmax[o] = mx; gpmin[o] = mn;
    }
    if(tid < 64){
        atomicAdd(&gsum[ob + tid], ssum[tid]);
        atomicAdd(&gsq [ob + tid], ssq [tid]);
    }
}

// ---------------- finalize BN params ----------------
__global__ void finalize_kernel(const float* __restrict__ gsum, const float* __restrict__ gsq,
                                const float* __restrict__ g, const float* __restrict__ bb,
                                float* __restrict__ sc, float* __restrict__ sh,
                                int Cout, double invM){
    int o = blockIdx.x*blockDim.x + threadIdx.x;
    if(o < Cout){
        double mean = (double)gsum[o]*invM;
        double var  = (double)gsq[o]*invM - mean*mean;
        float s = (float)((double)g[o] / sqrt(var + 1e-5));
        sc[o] = s;
        sh[o] = fmaf(-(float)mean, s, bb[o]);
    }
}

// ---------------- epilogue: BN+ReLU on pooled values ----------------
__global__ void bn_pool_out_kernel(const float* __restrict__ gpmax,
                                   const float* __restrict__ gpmin,
                                   const float* __restrict__ sc, const float* __restrict__ sh,
                                   float* __restrict__ out, int Cout, int coff){
    int i = blockIdx.x*blockDim.x + threadIdx.x;
    if(i >= Cout*NWIN) return;
    int win = i & (NWIN-1);
    int co  = i >> 13;
    int s = win & 1023, b = win >> 10;
    float s_ = sc[co], h_ = sh[co];
    float v = (s_ >= 0.f) ? gpmax[(size_t)co*NWIN + win] : gpmin[(size_t)co*NWIN + win];
    out[((size_t)(b*384 + coff + co))*SPTS + s] = fmaxf(0.f, fmaf(s_, v, h_));
}

// ---------------- launch ----------------
extern "C" void kernel_launch(void* const* d_in, const int* in_sizes, int n_in,
                              void* d_out, int out_size){
    const float* xyz  = (const float*)d_in[0];
    const float* feat = (const float*)d_in[1];
    const float *w[6], *g[6], *bb[6];
    for(int L=0; L<6; L++){
        w[L]  = (const float*)d_in[2 + L*3];
        g[L]  = (const float*)d_in[3 + L*3];
        bb[L] = (const float*)d_in[4 + L*3];
    }
    float* out = (float*)d_out;
    float* newxyz  = out;                         // (8,1024,3)
    float* outfeat = out + (size_t)BATCH*SPTS*3;  // (8,384,1024)

    void *pA0,*pB0,*pA1,*pB1,*pFT,*pM,*pI0,*pI1,*pSum,*pSq,*pSc,*pSh,*pPM,*pPN;
    cudaGetSymbolAddress(&pA0, d_bufA0);
    cudaGetSymbolAddress(&pB0, d_bufB0);
    cudaGetSymbolAddress(&pA1, d_bufA1);
    cudaGetSymbolAddress(&pB1, d_bufB1);
    cudaGetSymbolAddress(&pFT, d_featT);
    cudaGetSymbolAddress(&pM,  d_meanv);
    cudaGetSymbolAddress(&pI0, d_idx0);
    cudaGetSymbolAddress(&pI1, d_idx1);
    cudaGetSymbolAddress(&pSum,d_gsum);
    cudaGetSymbolAddress(&pSq, d_gsq);
    cudaGetSymbolAddress(&pSc, d_scl);
    cudaGetSymbolAddress(&pSh, d_shf);
    cudaGetSymbolAddress(&pPM, d_pmax);
    cudaGetSymbolAddress(&pPN, d_pmin);
    __half* A0 = (__half*)pA0; __half* B0 = (__half*)pB0;
    __half* A1 = (__half*)pA1; __half* B1 = (__half*)pB1;
    float* ft = (float*)pFT; float* mv = (float*)pM;
    int* i0 = (int*)pI0; int* i1 = (int*)pI1;
    float* gsum = (float*)pSum; float* gsq = (float*)pSq;
    float* scv = (float*)pSc; float* shv = (float*)pSh;
    float* pmax0 = (float*)pPM;                 float* pmin0 = (float*)pPN;
    float* pmax1 = pmax0 + (size_t)128*NWIN;    float* pmin1 = pmin0 + (size_t)128*NWIN;

    static cudaStream_t s1 = 0;
    static cudaEvent_t evF0 = 0, evF1 = 0, evT = 0, evJ = 0;
    static int attr_set = 0;
    const int FPS_SMEM = 3*N1*sizeof(float);
    if(!attr_set){
        cudaFuncSetAttribute(fps_kernel, cudaFuncAttributeMaxDynamicSharedMemorySize, FPS_SMEM);
        cudaFuncSetAttribute(gemm_g_kernel, cudaFuncAttributeMaxDynamicSharedMemorySize, G_SMEM);
        cudaStreamCreateWithFlags(&s1, cudaStreamNonBlocking);
        cudaEventCreateWithFlags(&evF0, cudaEventDisableTiming);
        cudaEventCreateWithFlags(&evF1, cudaEventDisableTiming);
        cudaEventCreateWithFlags(&evT,  cudaEventDisableTiming);
        cudaEventCreateWithFlags(&evJ,  cudaEventDisableTiming);
        attr_set = 1;
    }

    // ---- fork: transpose runs on side stream under FPS ----
    cudaEventRecord(evF0, 0);
    cudaStreamWaitEvent(s1, evF0, 0);
    transpose_kernel<<<dim3(NPTS/32, FEATC/32, BATCH), dim3(32,8), 0, s1>>>(feat, ft);
    cudaEventRecord(evT, s1);

    zero_stats_kernel<<<6,256>>>(gsum, gsq);
    mean_kernel<<<BATCH,256>>>(xyz, mv);
    fps_kernel<<<BATCH,1024,FPS_SMEM>>>(xyz, mv, newxyz);
    ballq_kernel<<<(BATCH*SPTS)/8, 256>>>(xyz, newxyz, i0, i1);
    cudaEventRecord(evF1, 0);

    // ---- branch 1 (r=0.8, ns=64): 67 -> 64 -> 128 -> 256  [side stream] ----
    cudaStreamWaitEvent(s1, evF1, 0);
    gemm_g_kernel<<<dim3(1, M1/256),256,G_SMEM,s1>>>(w[3], xyz, ft, newxyz, i1, A1, M1, NS1, gsum+3*256, gsq+3*256);
    finalize_kernel<<<1,256,0,s1>>>(gsum+3*256, gsq+3*256, g[3], bb[3], scv+3*256, shv+3*256, 64, 1.0/M1);
    gemm_tc_kernel<<<dim3(2, M1/256),256,0,s1>>>(w[4], A1, B1, 64, 128, M1, scv+3*256, shv+3*256, gsum+4*256, gsq+4*256);
    finalize_kernel<<<1,256,0,s1>>>(gsum+4*256, gsq+4*256, g[4], bb[4], scv+4*256, shv+4*256, 128, 1.0/M1);
    gemm_tc_pool_kernel<<<dim3(4, M1/256),256,0,s1>>>(w[5], B1, 128, 256, M1, NS1, scv+4*256, shv+4*256, gsum+5*256, gsq+5*256, pmax1, pmin1);
    finalize_kernel<<<1,256,0,s1>>>(gsum+5*256, gsq+5*256, g[5], bb[5], scv+5*256, shv+5*256, 256, 1.0/M1);
    bn_pool_out_kernel<<<(256*NWIN)/256,256,0,s1>>>(pmax1, pmin1, scv+5*256, shv+5*256, outfeat, 256, 128);
    cudaEventRecord(evJ, s1);

    // ---- branch 0 (r=0.4, ns=32): 67 -> 64 -> 64 -> 128  [main stream] ----
    cudaStreamWaitEvent(0, evT, 0);
    gemm_g_kernel<<<dim3(1, M0/256),256,G_SMEM>>>(w[0], xyz, ft, newxyz, i0, A0, M0, NS0, gsum+0*256, gsq+0*256);
    finalize_kernel<<<1,256>>>(gsum+0*256, gsq+0*256, g[0], bb[0], scv+0*256, shv+0*256, 64, 1.0/M0);
    gemm_tc_kernel<<<dim3(1, M0/256),256>>>(w[1], A0, B0, 64, 64, M0, scv+0*256, shv+0*256, gsum+1*256, gsq+1*256);
    finalize_kernel<<<1,256>>>(gsum+1*256, gsq+1*256, g[1], bb[1], scv+1*256, shv+1*256, 64, 1.0/M0);
    gemm_tc_pool_kernel<<<dim3(2, M0/256),256>>>(w[2], B0, 64, 128, M0, NS0, scv+1*256, shv+1*256, gsum+2*256, gsq+2*256, pmax0, pmin0);
    finalize_kernel<<<1,256>>>(gsum+2*256, gsq+2*256, g[2], bb[2], scv+2*256, shv+2*256, 128, 1.0/M0);
    bn_pool_out_kernel<<<(128*NWIN)/256,256>>>(pmax0, pmin0, scv+2*256, shv+2*256, outfeat, 128, 0);

    // ---- join ----
    cudaStreamWaitEvent(0, evJ, 0);
}

// round 17
// speedup vs baseline: 1.5947x; 1.5947x over previous
#include <cuda_runtime.h>
#include <cuda_fp16.h>
#include <cstdint>
#include <cstdio>

#define BATCH 8
#define NPTS 8192
#define N1 8193
#define SPTS 1024
#define FEATC 64
#define CIN0 67
#define NS0 32
#define NS1 64
#define M0 (BATCH*SPTS*NS0)   /* 262144 */
#define M1 (BATCH*SPTS*NS1)   /* 524288 */
#define NWIN 8192             /* M0/NS0 == M1/NS1 */

// ---------------- static scratch (allocation is forbidden) ----------------
// Intermediates stored as fp16 (consumer re-rounds to tf32 anyway).
__device__ __half  d_bufA0[(size_t)64*M0];
__device__ __half  d_bufB0[(size_t)64*M0];
__device__ __half  d_bufA1[(size_t)64*M1];
__device__ __half  d_bufB1[(size_t)128*M1];
__device__ float   d_featT[(size_t)BATCH*NPTS*FEATC];
__device__ float   d_pmax[(size_t)384*NWIN];
__device__ float   d_pmin[(size_t)384*NWIN];
__device__ float   d_meanv[BATCH*3];
__device__ int     d_idx0[(size_t)BATCH*SPTS*NS0];
__device__ int     d_idx1[(size_t)BATCH*SPTS*NS1];
__device__ float   d_gsum[6*256];
__device__ float   d_gsq [6*256];
__device__ float   d_scl [6*256];
__device__ float   d_shf [6*256];

// ---------------- tf32 / f32x2 helpers ----------------
typedef unsigned long long u64;
__device__ __forceinline__ float tf32r(float x){
    unsigned u; asm("cvt.rna.tf32.f32 %0, %1;" : "=r"(u) : "f"(x));
    return __uint_as_float(u);
}
__device__ __forceinline__ void mma8(float* c, const float* a, const float* b){
    asm volatile("mma.sync.aligned.m16n8k8.row.col.f32.tf32.tf32.f32 "
      "{%0,%1,%2,%3},{%4,%5,%6,%7},{%8,%9},{%0,%1,%2,%3};"
      : "+f"(c[0]),"+f"(c[1]),"+f"(c[2]),"+f"(c[3])
      : "r"(__float_as_uint(a[0])),"r"(__float_as_uint(a[1])),
        "r"(__float_as_uint(a[2])),"r"(__float_as_uint(a[3])),
        "r"(__float_as_uint(b[0])),"r"(__float_as_uint(b[1])));
}
__device__ __forceinline__ u64 pk2(float x, float y){
    u64 r; asm("mov.b64 %0, {%1,%2};" : "=l"(r) : "f"(x), "f"(y)); return r;
}
#define ADD2(d,a,b) asm("add.rn.f32x2 %0, %1, %2;" : "=l"(d) : "l"(a), "l"(b))
#define MUL2(d,a,b) asm("mul.rn.f32x2 %0, %1, %2;" : "=l"(d) : "l"(a), "l"(b))
#define UNPK2(lo,hi,v) asm("mov.b64 {%0,%1}, %2;" : "=f"(lo), "=f"(hi) : "l"(v))

// ---------------- zero stats ----------------
__global__ void zero_stats_kernel(float* gsum, float* gsq){
    int i = blockIdx.x*blockDim.x + threadIdx.x;
    if(i < 6*256){ gsum[i]=0.f; gsq[i]=0.f; }
}

// ---------------- mean over points ----------------
__global__ void mean_kernel(const float* __restrict__ xyz, float* __restrict__ meanv){
    int b = blockIdx.x, t = threadIdx.x;
    double sx=0, sy=0, sz=0;
    for(int n=t; n<NPTS; n+=256){
        const float* p = xyz + ((size_t)b*NPTS + n)*3;
        sx += (double)p[0]; sy += (double)p[1]; sz += (double)p[2];
    }
    __shared__ double rx[256], ry[256], rz[256];
    rx[t]=sx; ry[t]=sy; rz[t]=sz; __syncthreads();
    for(int o=128;o;o>>=1){
        if(t<o){ rx[t]+=rx[t+o]; ry[t]+=ry[t+o]; rz[t]+=rz[t+o]; }
        __syncthreads();
    }
    if(t==0){
        meanv[b*3+0]=(float)(rx[0]/NPTS);
        meanv[b*3+1]=(float)(ry[0]/NPTS);
        meanv[b*3+2]=(float)(rz[0]/NPTS);
    }
}

// ---------------- farthest point sampling ----------------
// Packed f32x2 distance math (per-lane IEEE-RN identical to scalar,
// no FMA contraction) + redux.sync argmax (candidates >= 0 so uint
// order == float order; min-index tie-break = first occurrence).
__global__ __launch_bounds__(1024) void fps_kernel(const float* __restrict__ xyz,
                                                   const float* __restrict__ meanv,
                                                   float* __restrict__ newxyz){
    extern __shared__ float sh[];          // sx[N1], sy[N1], sz[N1]
    float* sx = sh;
    float* sy = sh + N1;
    float* sz = sh + 2*N1;
    __shared__ unsigned swv[2][32]; __shared__ int swi[2][32];
    int b = blockIdx.x, t = threadIdx.x;
    int lane = t & 31, wrp = t >> 5;

    for(int i=t; i<N1; i+=1024){
        if(i==0){ sx[0]=meanv[b*3]; sy[0]=meanv[b*3+1]; sz[0]=meanv[b*3+2]; }
        else{
            const float* p = xyz + ((size_t)b*NPTS + (i-1))*3;
            sx[i]=p[0]; sy[i]=p[1]; sz[i]=p[2];
        }
    }
    __syncthreads();

    u64 pxp[4], pyp[4], pzp[4];
    float dist[8];
    #pragma unroll
    for(int q=0;q<4;q++){
        int i0 = t + (2*q)*1024, i1 = t + (2*q+1)*1024;
        pxp[q] = pk2(sx[i0], sx[i1]);
        pyp[q] = pk2(sy[i0], sy[i1]);
        pzp[q] = pk2(sz[i0], sz[i1]);
        dist[2*q] = 1e10f; dist[2*q+1] = 1e10f;
    }
    float px8=0.f, py8=0.f, pz8=0.f, dist8=1e10f;
    if(t==0){ px8=sx[8192]; py8=sy[8192]; pz8=sz[8192]; }

    float cx = sx[0], cy = sy[0], cz = sz[0];
    int par = 0;
    for(int s=0;s<SPTS;s++){
        if(t==0){
            float* o = newxyz + ((size_t)b*SPTS + s)*3;
            o[0]=cx; o[1]=cy; o[2]=cz;
        }
        float ncx = -cx, ncy = -cy, ncz = -cz;
        u64 cxp = pk2(ncx,ncx), cyp = pk2(ncy,ncy), czp = pk2(ncz,ncz);
        float bv = -2.0f; int bi = 0;
        #pragma unroll
        for(int q=0;q<4;q++){
            u64 dx, dy, dz, xx, yy, zz, s1, dd;
            ADD2(dx, pxp[q], cxp);
            ADD2(dy, pyp[q], cyp);
            ADD2(dz, pzp[q], czp);
            MUL2(xx, dx, dx);
            MUL2(yy, dy, dy);
            MUL2(zz, dz, dz);
            ADD2(s1, xx, yy);
            ADD2(dd, s1, zz);
            float d0, d1; UNPK2(d0, d1, dd);
            float nd0 = fminf(dist[2*q], d0);   dist[2*q] = nd0;
            if(nd0 > bv){ bv = nd0; bi = t + (2*q)*1024; }
            float nd1 = fminf(dist[2*q+1], d1); dist[2*q+1] = nd1;
            if(nd1 > bv){ bv = nd1; bi = t + (2*q+1)*1024; }
        }
        if(t==0){
            float dx = __fadd_rn(px8, ncx);
            float dy = __fadd_rn(py8, ncy);
            float dz = __fadd_rn(pz8, ncz);
            float d  = __fadd_rn(__fadd_rn(__fmul_rn(dx,dx), __fmul_rn(dy,dy)), __fmul_rn(dz,dz));
            float nd = fminf(dist8, d); dist8 = nd;
            if(nd > bv){ bv = nd; bi = 8192; }
        }
        unsigned u = __float_as_uint(bv);
        unsigned m = __reduce_max_sync(0xffffffffu, u);
        int cand = (u == m) ? bi : 0x7fffffff;
        int wmin = __reduce_min_sync(0xffffffffu, cand);
        if(lane == 0){ swv[par][wrp] = m; swi[par][wrp] = wmin; }
        __syncthreads();
        unsigned u2 = swv[par][lane]; int j2 = swi[par][lane];
        unsigned m2 = __reduce_max_sync(0xffffffffu, u2);
        int cand2 = (u2 == m2) ? j2 : 0x7fffffff;
        int far = __reduce_min_sync(0xffffffffu, cand2);
        cx = sx[far]; cy = sy[far]; cz = sz[far];
        par ^= 1;
    }
}

// ---------------- feature transpose (B,C,N) -> (B,N,C) ----------------
__global__ void transpose_kernel(const float* __restrict__ f, float* __restrict__ ft){
    __shared__ float tile[32][33];
    int b = blockIdx.z;
    int n0 = blockIdx.x*32, c0 = blockIdx.y*32;
    int tx = threadIdx.x, ty = threadIdx.y;
    #pragma unroll
    for(int i=0;i<32;i+=8)
        tile[ty+i][tx] = f[((size_t)b*FEATC + (c0+ty+i))*NPTS + n0 + tx];
    __syncthreads();
    #pragma unroll
    for(int i=0;i<32;i+=8)
        ft[((size_t)b*NPTS + (n0+ty+i))*FEATC + c0 + tx] = tile[tx][ty+i];
}

// ---------------- ball query (both radii in one pass) ----------------
__global__ __launch_bounds__(256) void ballq_kernel(const float* __restrict__ xyz,
                                                    const float* __restrict__ nx,
                                                    int* __restrict__ idx0,
                                                    int* __restrict__ idx1){
    int gw = (blockIdx.x*blockDim.x + threadIdx.x) >> 5;
    int lane = threadIdx.x & 31;
    int b = gw >> 10, s = gw & 1023;
    const float R20 = (float)(0.4*0.4);
    const float R21 = (float)(0.8*0.8);
    const float* cp = nx + ((size_t)b*SPTS + s)*3;
    float cx=cp[0], cy=cp[1], cz=cp[2];
    int cnt0=0, cnt1=0, first0=0, first1=0;
    size_t base0 = ((size_t)b*SPTS + s)*NS0;
    size_t base1 = ((size_t)b*SPTS + s)*NS1;
    unsigned lmask = (1u << lane) - 1u;
    for(int ch=0; ch<NPTS/32; ch++){
        if(cnt0 >= NS0 && cnt1 >= NS1) break;
        int n = ch*32 + lane;
        const float* p = xyz + ((size_t)b*NPTS + n)*3;
        float dx = __fadd_rn(cx, -p[0]);
        float dy = __fadd_rn(cy, -p[1]);
        float dz = __fadd_rn(cz, -p[2]);
        float d2 = __fadd_rn(__fadd_rn(__fmul_rn(dx,dx), __fmul_rn(dy,dy)), __fmul_rn(dz,dz));
        unsigned m1 = __ballot_sync(0xffffffffu, d2 < R21);
        unsigned m0 = __ballot_sync(0xffffffffu, d2 < R20);
        if(m0 && cnt0 < NS0){
            if(cnt0 == 0) first0 = ch*32 + __ffs(m0) - 1;
            if((m0 >> lane) & 1){
                int r = __popc(m0 & lmask);
                if(cnt0 + r < NS0) idx0[base0 + cnt0 + r] = n;
            }
            cnt0 = min(NS0, cnt0 + __popc(m0));
        }
        if(m1 && cnt1 < NS1){
            if(cnt1 == 0) first1 = ch*32 + __ffs(m1) - 1;
            if((m1 >> lane) & 1){
                int r = __popc(m1 & lmask);
                if(cnt1 + r < NS1) idx1[base1 + cnt1 + r] = n;
            }
            cnt1 = min(NS1, cnt1 + __popc(m1));
        }
    }
    int p0 = (cnt0 > 0) ? first0 : 0;
    for(int k=cnt0+lane; k<NS0; k+=32) idx0[base0+k] = p0;
    int p1 = (cnt1 > 0) ? first1 : 0;
    for(int k=cnt1+lane; k<NS1; k+=32) idx1[base1+k] = p1;
}

// ==================================================================
// Fused gather + tensor-core GEMM (layer 0). Y stored as fp16.
// ==================================================================
#define GX_STRIDE 264
#define GX_ROWS   80
#define G_SMEM    ((GX_ROWS*GX_STRIDE + 64*20)*4)

__global__ __launch_bounds__(256) void gemm_g_kernel(const float* __restrict__ W,
        const float* __restrict__ xyz, const float* __restrict__ ft,
        const float* __restrict__ nx, const int* __restrict__ idx,
        __half* __restrict__ Y, int M, int ns,
        float* __restrict__ gsum, float* __restrict__ gsq){
    extern __shared__ float dsm[];
    float* Xs = dsm;                       // [80][264]
    float* Wc = dsm + GX_ROWS*GX_STRIDE;   // [64][20]
    __shared__ float ssum[64], ssq[64];
    int tid = threadIdx.x;
    int lane = tid & 31, wn = tid >> 5;
    int g = lane >> 2, tg = lane & 3;
    int m0 = blockIdx.y * 256;
    if(tid < 64){ ssum[tid]=0.f; ssq[tid]=0.f; }

    // prefetch W chunk 0
    float wreg[4];
    #pragma unroll
    for(int i=0;i<4;i++){
        int ix = tid + i*256;
        int o = ix >> 4, k = ix & 15;
        wreg[i] = (k < CIN0) ? W[(size_t)o*CIN0 + k] : 0.f;
    }

    {
        int m = m0 + tid;
        int sc_ = m / ns;
        int s = sc_ & 1023, b = sc_ >> 10;
        int id = idx[m];
        const float* p = xyz + ((size_t)b*NPTS + id)*3;
        const float* c = nx  + ((size_t)b*SPTS + s)*3;
        Xs[0*GX_STRIDE + tid] = tf32r(p[0]-c[0]);
        Xs[1*GX_STRIDE + tid] = tf32r(p[1]-c[1]);
        Xs[2*GX_STRIDE + tid] = tf32r(p[2]-c[2]);
        const float4* fr = (const float4*)(ft + ((size_t)b*NPTS + id)*FEATC);
        #pragma unroll
        for(int j=0;j<16;j++){
            float4 v = fr[j];
            Xs[(3+4*j+0)*GX_STRIDE + tid] = tf32r(v.x);
            Xs[(3+4*j+1)*GX_STRIDE + tid] = tf32r(v.y);
            Xs[(3+4*j+2)*GX_STRIDE + tid] = tf32r(v.z);
            Xs[(3+4*j+3)*GX_STRIDE + tid] = tf32r(v.w);
        }
        #pragma unroll
        for(int k=CIN0;k<GX_ROWS;k++) Xs[k*GX_STRIDE + tid] = 0.f;
    }

    float acc[4][4][4];
    #pragma unroll
    for(int mt=0;mt<4;mt++)
        #pragma unroll
        for(int nt=0;nt<4;nt++)
            #pragma unroll
            for(int i=0;i<4;i++) acc[mt][nt][i]=0.f;
    __syncthreads();

    for(int kc=0; kc<5; kc++){
        int kb = kc*16;
        #pragma unroll
        for(int i=0;i<4;i++){
            int ix = tid + i*256;
            int o = ix >> 4, k = ix & 15;
            Wc[o*20 + k] = tf32r(wreg[i]);
        }
        __syncthreads();
        if(kc < 4){
            int kb2 = kb + 16;
            #pragma unroll
            for(int i=0;i<4;i++){
                int ix = tid + i*256;
                int o = ix >> 4, k = ix & 15;
                wreg[i] = (kb2 + k < CIN0) ? W[(size_t)o*CIN0 + kb2 + k] : 0.f;
            }
        }
        #pragma unroll
        for(int s8=0; s8<2; s8++){
            int ko = kb + s8*8, kl = s8*8;
            float a[4][4], b[4][2];
            #pragma unroll
            for(int mt=0;mt<4;mt++){
                int r0 = (mt*16 + g)*20 + kl + tg;
                a[mt][0] = Wc[r0];
                a[mt][1] = Wc[r0 + 160];
                a[mt][2] = Wc[r0 + 4];
                a[mt][3] = Wc[r0 + 164];
            }
            #pragma unroll
            for(int nt=0;nt<4;nt++){
                int cb = wn*32 + nt*8 + g;
                b[nt][0] = Xs[(ko+tg)*GX_STRIDE + cb];
                b[nt][1] = Xs[(ko+tg+4)*GX_STRIDE + cb];
            }
            #pragma unroll
            for(int mt=0;mt<4;mt++)
                #pragma unroll
                for(int nt=0;nt<4;nt++)
                    mma8(acc[mt][nt], a[mt], b[nt]);
        }
        __syncthreads();
    }

    float s8v[8], q8v[8];
    #pragma unroll
    for(int i=0;i<8;i++){ s8v[i]=0.f; q8v[i]=0.f; }
    #pragma unroll
    for(int mt=0;mt<4;mt++)
        #pragma unroll
        for(int nt=0;nt<4;nt++){
            float c0=acc[mt][nt][0], c1=acc[mt][nt][1];
            float c2=acc[mt][nt][2], c3=acc[mt][nt][3];
            s8v[mt*2+0] += c0+c1; q8v[mt*2+0] += c0*c0 + c1*c1;
            s8v[mt*2+1] += c2+c3; q8v[mt*2+1] += c2*c2 + c3*c3;
        }
    #pragma unroll
    for(int i=0;i<8;i++){
        s8v[i] += __shfl_xor_sync(0xffffffffu, s8v[i], 1);
        s8v[i] += __shfl_xor_sync(0xffffffffu, s8v[i], 2);
        q8v[i] += __shfl_xor_sync(0xffffffffu, q8v[i], 1);
        q8v[i] += __shfl_xor_sync(0xffffffffu, q8v[i], 2);
    }
    if(tg == 0){
        #pragma unroll
        for(int mt=0;mt<4;mt++){
            atomicAdd(&ssum[mt*16 + g],     s8v[mt*2+0]);
            atomicAdd(&ssq [mt*16 + g],     q8v[mt*2+0]);
            atomicAdd(&ssum[mt*16 + g + 8], s8v[mt*2+1]);
            atomicAdd(&ssq [mt*16 + g + 8], q8v[mt*2+1]);
        }
    }
    #pragma unroll
    for(int mt=0;mt<4;mt++)
        #pragma unroll
        for(int nt=0;nt<4;nt++){
            int m = m0 + wn*32 + nt*8 + 2*tg;
            int r0 = mt*16 + g;
            *(__half2*)(Y + (size_t)r0*M + m)     = __floats2half2_rn(acc[mt][nt][0], acc[mt][nt][1]);
            *(__half2*)(Y + (size_t)(r0+8)*M + m) = __floats2half2_rn(acc[mt][nt][2], acc[mt][nt][3]);
        }
    __syncthreads();
    if(tid < 64){
        atomicAdd(&gsum[tid], ssum[tid]);
        atomicAdd(&gsq [tid], ssq [tid]);
    }
}

// ==================================================================
// Middle-layer GEMM: fp16 in, fp16 out; double-buffered staging.
// ==================================================================
__global__ __launch_bounds__(256) void gemm_tc_kernel(const float* __restrict__ W,
        const __half* __restrict__ X, __half* __restrict__ Y,
        int Cin, int Cout, int M,
        const float* __restrict__ tsc, const float* __restrict__ tsh,
        float* __restrict__ gsum, float* __restrict__ gsq){
    __shared__ float Xs[16*264];
    __shared__ float Wc[64*20];
    __shared__ float ssum[64], ssq[64];
    int tid = threadIdx.x;
    int lane = tid & 31, wn = tid >> 5;
    int g = lane >> 2, tg = lane & 3;
    int ob = blockIdx.x * 64;
    int m0 = blockIdx.y * 256;
    int rr = tid >> 4, cb = (tid & 15)*16;
    if(tid < 64){ ssum[tid]=0.f; ssq[tid]=0.f; }

    float acc[4][4][4];
    #pragma unroll
    for(int mt=0;mt<4;mt++)
        #pragma unroll
        for(int nt=0;nt<4;nt++)
            #pragma unroll
            for(int i=0;i<4;i++) acc[mt][nt][i]=0.f;

    int kchunks = (Cin + 15) >> 4;

    // prefetch chunk 0 (16 halves = 2 x uint4)
    uint4 xreg[2]; float wreg[4];
    {
        int cin = rr;
        if(cin < Cin){
            const uint4* p = (const uint4*)(X + (size_t)cin*M + m0 + cb);
            xreg[0] = p[0]; xreg[1] = p[1];
        } else {
            xreg[0] = make_uint4(0,0,0,0); xreg[1] = make_uint4(0,0,0,0);
        }
        #pragma unroll
        for(int i=0;i<4;i++){
            int ix = tid + i*256;
            int o = ix >> 4, k = ix & 15;
            wreg[i] = (k < Cin) ? W[(size_t)(ob+o)*Cin + k] : 0.f;
        }
    }

    for(int kc=0; kc<kchunks; kc++){
        int kb = kc*16;
        // ---- store staged chunk to SMEM (h2f + BN + tf32r here) ----
        {
            int cin = kb + rr;
            float v[16];
            const __half2* hp = (const __half2*)xreg;
            #pragma unroll
            for(int j=0;j<8;j++){
                float2 f = __half22float2(hp[j]);
                v[2*j] = f.x; v[2*j+1] = f.y;
            }
            if(cin < Cin){
                float s_ = tsc[cin], h_ = tsh[cin];
                #pragma unroll
                for(int j=0;j<16;j++) v[j] = tf32r(fmaxf(0.f, fmaf(s_, v[j], h_)));
            }
            #pragma unroll
            for(int j=0;j<16;j++) Xs[rr*264 + cb + j] = v[j];
        }
        #pragma unroll
        for(int i=0;i<4;i++){
            int ix = tid + i*256;
            int o = ix >> 4, k = ix & 15;
            Wc[o*20 + k] = tf32r(wreg[i]);
        }
        __syncthreads();
        // ---- prefetch next chunk ----
        if(kc + 1 < kchunks){
            int kb2 = kb + 16;
            int cin = kb2 + rr;
            if(cin < Cin){
                const uint4* p = (const uint4*)(X + (size_t)cin*M + m0 + cb);
                xreg[0] = p[0]; xreg[1] = p[1];
            } else {
                xreg[0] = make_uint4(0,0,0,0); xreg[1] = make_uint4(0,0,0,0);
            }
            #pragma unroll
            for(int i=0;i<4;i++){
                int ix = tid + i*256;
                int o = ix >> 4, k = ix & 15;
                wreg[i] = (kb2 + k < Cin) ? W[(size_t)(ob+o)*Cin + kb2 + k] : 0.f;
            }
        }
        // ---- MMAs for current chunk ----
        #pragma unroll
        for(int s8=0; s8<2; s8++){
            int ko = s8*8;
            float a[4][4], b[4][2];
            #pragma unroll
            for(int mt=0;mt<4;mt++){
                int r0 = (mt*16 + g)*20 + ko + tg;
                a[mt][0] = Wc[r0];
                a[mt][1] = Wc[r0 + 160];
                a[mt][2] = Wc[r0 + 4];
                a[mt][3] = Wc[r0 + 164];
            }
            #pragma unroll
            for(int nt=0;nt<4;nt++){
                int cbw = wn*32 + nt*8 + g;
                b[nt][0] = Xs[(ko+tg)*264 + cbw];
                b[nt][1] = Xs[(ko+tg+4)*264 + cbw];
            }
            #pragma unroll
            for(int mt=0;mt<4;mt++)
                #pragma unroll
                for(int nt=0;nt<4;nt++)
                    mma8(acc[mt][nt], a[mt], b[nt]);
        }
        __syncthreads();
    }

    float s8v[8], q8v[8];
    #pragma unroll
    for(int i=0;i<8;i++){ s8v[i]=0.f; q8v[i]=0.f; }
    #pragma unroll
    for(int mt=0;mt<4;mt++)
        #pragma unroll
        for(int nt=0;nt<4;nt++){
            float c0=acc[mt][nt][0], c1=acc[mt][nt][1];
            float c2=acc[mt][nt][2], c3=acc[mt][nt][3];
            s8v[mt*2+0] += c0+c1; q8v[mt*2+0] += c0*c0 + c1*c1;
            s8v[mt*2+1] += c2+c3; q8v[mt*2+1] += c2*c2 + c3*c3;
        }
    #pragma unroll
    for(int i=0;i<8;i++){
        s8v[i] += __shfl_xor_sync(0xffffffffu, s8v[i], 1);
        s8v[i] += __shfl_xor_sync(0xffffffffu, s8v[i], 2);
        q8v[i] += __shfl_xor_sync(0xffffffffu, q8v[i], 1);
        q8v[i] += __shfl_xor_sync(0xffffffffu, q8v[i], 2);
    }
    if(tg == 0){
        #pragma unroll
        for(int mt=0;mt<4;mt++){
            atomicAdd(&ssum[mt*16 + g],     s8v[mt*2+0]);
            atomicAdd(&ssq [mt*16 + g],     q8v[mt*2+0]);
            atomicAdd(&ssum[mt*16 + g + 8], s8v[mt*2+1]);
            atomicAdd(&ssq [mt*16 + g + 8], q8v[mt*2+1]);
        }
    }
    #pragma unroll
    for(int mt=0;mt<4;mt++)
        #pragma unroll
        for(int nt=0;nt<4;nt++){
            int m = m0 + wn*32 + nt*8 + 2*tg;
            int r0 = ob + mt*16 + g;
            *(__half2*)(Y + (size_t)r0*M + m)     = __floats2half2_rn(acc[mt][nt][0], acc[mt][nt][1]);
            *(__half2*)(Y + (size_t)(r0+8)*M + m) = __floats2half2_rn(acc[mt][nt][2], acc[mt][nt][3]);
        }
    __syncthreads();
    if(tid < 64){
        atomicAdd(&gsum[ob + tid], ssum[tid]);
        atomicAdd(&gsq [ob + tid], ssq [tid]);
    }
}

// ==================================================================
// Last-layer GEMM: fp16 in; no Y store; stats + pooled raw max/min (fp32).
// ==================================================================
__global__ __launch_bounds__(256) void gemm_tc_pool_kernel(const float* __restrict__ W,
        const __half* __restrict__ X, int Cin, int Cout, int M, int ns,
        const float* __restrict__ tsc, const float* __restrict__ tsh,
        float* __restrict__ gsum, float* __restrict__ gsq,
        float* __restrict__ gpmax, float* __restrict__ gpmin){
    __shared__ float Xs[16*264];
    __shared__ float Wc[64*20];
    __shared__ float ssum[64], ssq[64];
    __shared__ float pmaxS[64][8], pminS[64][8];
    int tid = threadIdx.x;
    int lane = tid & 31, wn = tid >> 5;
    int g = lane >> 2, tg = lane & 3;
    int ob = blockIdx.x * 64;
    int m0 = blockIdx.y * 256;
    int rr = tid >> 4, cb = (tid & 15)*16;
    if(tid < 64){ ssum[tid]=0.f; ssq[tid]=0.f; }

    float acc[4][4][4];
    #pragma unroll
    for(int mt=0;mt<4;mt++)
        #pragma unroll
        for(int nt=0;nt<4;nt++)
            #pragma unroll
            for(int i=0;i<4;i++) acc[mt][nt][i]=0.f;

    int kchunks = (Cin + 15) >> 4;

    uint4 xreg[2]; float wreg[4];
    {
        int cin = rr;
        if(cin < Cin){
            const uint4* p = (const uint4*)(X + (size_t)cin*M + m0 + cb);
            xreg[0] = p[0]; xreg[1] = p[1];
        } else {
            xreg[0] = make_uint4(0,0,0,0); xreg[1] = make_uint4(0,0,0,0);
        }
        #pragma unroll
        for(int i=0;i<4;i++){
            int ix = tid + i*256;
            int o = ix >> 4, k = ix & 15;
            wreg[i] = (k < Cin) ? W[(size_t)(ob+o)*Cin + k] : 0.f;
        }
    }

    for(int kc=0; kc<kchunks; kc++){
        int kb = kc*16;
        {
            int cin = kb + rr;
            float v[16];
            const __half2* hp = (const __half2*)xreg;
            #pragma unroll
            for(int j=0;j<8;j++){
                float2 f = __half22float2(hp[j]);
                v[2*j] = f.x; v[2*j+1] = f.y;
            }
            if(cin < Cin){
                float s_ = tsc[cin], h_ = tsh[cin];
                #pragma unroll
                for(int j=0;j<16;j++) v[j] = tf32r(fmaxf(0.f, fmaf(s_, v[j], h_)));
            }
            #pragma unroll
            for(int j=0;j<16;j++) Xs[rr*264 + cb + j] = v[j];
        }
        #pragma unroll
        for(int i=0;i<4;i++){
            int ix = tid + i*256;
            int o = ix >> 4, k = ix & 15;
            Wc[o*20 + k] = tf32r(wreg[i]);
        }
        __syncthreads();
        if(kc + 1 < kchunks){
            int kb2 = kb + 16;
            int cin = kb2 + rr;
            if(cin < Cin){
                const uint4* p = (const uint4*)(X + (size_t)cin*M + m0 + cb);
                xreg[0] = p[0]; xreg[1] = p[1];
            } else {
                xreg[0] = make_uint4(0,0,0,0); xreg[1] = make_uint4(0,0,0,0);
            }
            #pragma unroll
            for(int i=0;i<4;i++){
                int ix = tid + i*256;
                int o = ix >> 4, k = ix & 15;
                wreg[i] = (kb2 + k < Cin) ? W[(size_t)(ob+o)*Cin + kb2 + k] : 0.f;
            }
        }
        #pragma unroll
        for(int s8=0; s8<2; s8++){
            int ko = s8*8;
            float a[4][4], b[4][2];
            #pragma unroll
            for(int mt=0;mt<4;mt++){
                int r0 = (mt*16 + g)*20 + ko + tg;
                a[mt][0] = Wc[r0];
                a[mt][1] = Wc[r0 + 160];
                a[mt][2] = Wc[r0 + 4];
                a[mt][3] = Wc[r0 + 164];
            }
            #pragma unroll
            for(int nt=0;nt<4;nt++){
                int cbw = wn*32 + nt*8 + g;
                b[nt][0] = Xs[(ko+tg)*264 + cbw];
                b[nt][1] = Xs[(ko+tg+4)*264 + cbw];
            }
            #pragma unroll
            for(int mt=0;mt<4;mt++)
                #pragma unroll
                for(int nt=0;nt<4;nt++)
                    mma8(acc[mt][nt], a[mt], b[nt]);
        }
        __syncthreads();
    }

    float s8v[8], q8v[8];
    #pragma unroll
    for(int i=0;i<8;i++){ s8v[i]=0.f; q8v[i]=0.f; }
    #pragma unroll
    for(int mt=0;mt<4;mt++)
        #pragma unroll
        for(int nt=0;nt<4;nt++){
            float c0=acc[mt][nt][0], c1=acc[mt][nt][1];
            float c2=acc[mt][nt][2], c3=acc[mt][nt][3];
            s8v[mt*2+0] += c0+c1; q8v[mt*2+0] += c0*c0 + c1*c1;
            s8v[mt*2+1] += c2+c3; q8v[mt*2+1] += c2*c2 + c3*c3;
        }
    #pragma unroll
    for(int i=0;i<8;i++){
        s8v[i] += __shfl_xor_sync(0xffffffffu, s8v[i], 1);
        s8v[i] += __shfl_xor_sync(0xffffffffu, s8v[i], 2);
        q8v[i] += __shfl_xor_sync(0xffffffffu, q8v[i], 1);
        q8v[i] += __shfl_xor_sync(0xffffffffu, q8v[i], 2);
    }
    if(tg == 0){
        #pragma unroll
        for(int mt=0;mt<4;mt++){
            atomicAdd(&ssum[mt*16 + g],     s8v[mt*2+0]);
            atomicAdd(&ssq [mt*16 + g],     q8v[mt*2+0]);
            atomicAdd(&ssum[mt*16 + g + 8], s8v[mt*2+1]);
            atomicAdd(&ssq [mt*16 + g + 8], q8v[mt*2+1]);
        }
    }

    #pragma unroll
    for(int mt=0;mt<4;mt++){
        float mxA=-3.4e38f, mnA=3.4e38f, mxB=-3.4e38f, mnB=3.4e38f;
        #pragma unroll
        for(int nt=0;nt<4;nt++){
            mxA = fmaxf(mxA, fmaxf(acc[mt][nt][0], acc[mt][nt][1]));
            mnA = fminf(mnA, fminf(acc[mt][nt][0], acc[mt][nt][1]));
            mxB = fmaxf(mxB, fmaxf(acc[mt][nt][2], acc[mt][nt][3]));
            mnB = fminf(mnB, fminf(acc[mt][nt][2], acc[mt][nt][3]));
        }
        #pragma unroll
        for(int o=1;o<=2;o<<=1){
            mxA = fmaxf(mxA, __shfl_xor_sync(0xffffffffu, mxA, o));
            mnA = fminf(mnA, __shfl_xor_sync(0xffffffffu, mnA, o));
            mxB = fmaxf(mxB, __shfl_xor_sync(0xffffffffu, mxB, o));
            mnB = fminf(mnB, __shfl_xor_sync(0xffffffffu, mnB, o));
        }
        if(tg == 0){
            pmaxS[mt*16 + g][wn] = mxA;   pminS[mt*16 + g][wn] = mnA;
            pmaxS[mt*16 + g + 8][wn] = mxB; pminS[mt*16 + g + 8][wn] = mnB;
        }
    }
    __syncthreads();
    int nwin = 256/ns;
    int gsz  = ns/32;
    for(int i=tid; i<64*nwin; i+=256){
        int row = i / nwin, win = i % nwin;
        float mx=-3.4e38f, mn=3.4e38f;
        for(int j=0;j<gsz;j++){
            mx = fmaxf(mx, pmaxS[row][win*gsz + j]);
            mn = fminf(mn, pminS[row][win*gsz + j]);
        }
        size_t o = (size_t)(ob + row)*NWIN + m0/ns + win;
        gpmax[o] = mx; gpmin[o] = mn;
    }
    if(tid < 64){
        atomicAdd(&gsum[ob + tid], ssum[tid]);
        atomicAdd(&gsq [ob + tid], ssq [tid]);
    }
}

// ---------------- finalize BN params ----------------
__global__ void finalize_kernel(const float* __restrict__ gsum, const float* __restrict__ gsq,
                                const float* __restrict__ g, const float* __restrict__ bb,
                                float* __restrict__ sc, float* __restrict__ sh,
                                int Cout, double invM){
    int o = blockIdx.x*blockDim.x + threadIdx.x;
    if(o < Cout){
        double mean = (double)gsum[o]*invM;
        double var  = (double)gsq[o]*invM - mean*mean;
        float s = (float)((double)g[o] / sqrt(var + 1e-5));
        sc[o] = s;
        sh[o] = fmaf(-(float)mean, s, bb[o]);
    }
}

// ---------------- epilogue: BN+ReLU on pooled values ----------------
__global__ void bn_pool_out_kernel(const float* __restrict__ gpmax,
                                   const float* __restrict__ gpmin,
                                   const float* __restrict__ sc, const float* __restrict__ sh,
                                   float* __restrict__ out, int Cout, int coff){
    int i = blockIdx.x*blockDim.x + threadIdx.x;
    if(i >= Cout*NWIN) return;
    int win = i & (NWIN-1);
    int co  = i >> 13;
    int s = win & 1023, b = win >> 10;
    float s_ = sc[co], h_ = sh[co];
    float v = (s_ >= 0.f) ? gpmax[(size_t)co*NWIN + win] : gpmin[(size_t)co*NWIN + win];
    out[((size_t)(b*384 + coff + co))*SPTS + s] = fmaxf(0.f, fmaf(s_, v, h_));
}

// ---------------- launch ----------------
extern "C" void kernel_launch(void* const* d_in, const int* in_sizes, int n_in,
                              void* d_out, int out_size){
    const float* xyz  = (const float*)d_in[0];
    const float* feat = (const float*)d_in[1];
    const float *w[6], *g[6], *bb[6];
    for(int L=0; L<6; L++){
        w[L]  = (const float*)d_in[2 + L*3];
        g[L]  = (const float*)d_in[3 + L*3];
        bb[L] = (const float*)d_in[4 + L*3];
    }
    float* out = (float*)d_out;
    float* newxyz  = out;                         // (8,1024,3)
    float* outfeat = out + (size_t)BATCH*SPTS*3;  // (8,384,1024)

    void *pA0,*pB0,*pA1,*pB1,*pFT,*pM,*pI0,*pI1,*pSum,*pSq,*pSc,*pSh,*pPM,*pPN;
    cudaGetSymbolAddress(&pA0, d_bufA0);
    cudaGetSymbolAddress(&pB0, d_bufB0);
    cudaGetSymbolAddress(&pA1, d_bufA1);
    cudaGetSymbolAddress(&pB1, d_bufB1);
    cudaGetSymbolAddress(&pFT, d_featT);
    cudaGetSymbolAddress(&pM,  d_meanv);
    cudaGetSymbolAddress(&pI0, d_idx0);
    cudaGetSymbolAddress(&pI1, d_idx1);
    cudaGetSymbolAddress(&pSum,d_gsum);
    cudaGetSymbolAddress(&pSq, d_gsq);
    cudaGetSymbolAddress(&pSc, d_scl);
    cudaGetSymbolAddress(&pSh, d_shf);
    cudaGetSymbolAddress(&pPM, d_pmax);
    cudaGetSymbolAddress(&pPN, d_pmin);
    __half* A0 = (__half*)pA0; __half* B0 = (__half*)pB0;
    __half* A1 = (__half*)pA1; __half* B1 = (__half*)pB1;
    float* ft = (float*)pFT; float* mv = (float*)pM;
    int* i0 = (int*)pI0; int* i1 = (int*)pI1;
    float* gsum = (float*)pSum; float* gsq = (float*)pSq;
    float* scv = (float*)pSc; float* shv = (float*)pSh;
    float* pmax0 = (float*)pPM;                 float* pmin0 = (float*)pPN;
    float* pmax1 = pmax0 + (size_t)128*NWIN;    float* pmin1 = pmin0 + (size_t)128*NWIN;

    static cudaStream_t s1 = 0;
    static cudaEvent_t evF0 = 0, evF1 = 0, evT = 0, evJ = 0;
    static int attr_set = 0;
    const int FPS_SMEM = 3*N1*sizeof(float);
    if(!attr_set){
        cudaFuncSetAttribute(fps_kernel, cudaFuncAttributeMaxDynamicSharedMemorySize, FPS_SMEM);
        cudaFuncSetAttribute(gemm_g_kernel, cudaFuncAttributeMaxDynamicSharedMemorySize, G_SMEM);
        cudaStreamCreateWithFlags(&s1, cudaStreamNonBlocking);
        cudaEventCreateWithFlags(&evF0, cudaEventDisableTiming);
        cudaEventCreateWithFlags(&evF1, cudaEventDisableTiming);
        cudaEventCreateWithFlags(&evT,  cudaEventDisableTiming);
        cudaEventCreateWithFlags(&evJ,  cudaEventDisableTiming);
        attr_set = 1;
    }

    // ---- fork: transpose runs on side stream under FPS ----
    cudaEventRecord(evF0, 0);
    cudaStreamWaitEvent(s1, evF0, 0);
    transpose_kernel<<<dim3(NPTS/32, FEATC/32, BATCH), dim3(32,8), 0, s1>>>(feat, ft);
    cudaEventRecord(evT, s1);

    zero_stats_kernel<<<6,256>>>(gsum, gsq);
    mean_kernel<<<BATCH,256>>>(xyz, mv);
    fps_kernel<<<BATCH,1024,FPS_SMEM>>>(xyz, mv, newxyz);
    ballq_kernel<<<(BATCH*SPTS)/8, 256>>>(xyz, newxyz, i0, i1);
    cudaEventRecord(evF1, 0);

    // ---- branch 1 (r=0.8, ns=64): 67 -> 64 -> 128 -> 256  [side stream] ----
    cudaStreamWaitEvent(s1, evF1, 0);
    gemm_g_kernel<<<dim3(1, M1/256),256,G_SMEM,s1>>>(w[3], xyz, ft, newxyz, i1, A1, M1, NS1, gsum+3*256, gsq+3*256);
    finalize_kernel<<<1,256,0,s1>>>(gsum+3*256, gsq+3*256, g[3], bb[3], scv+3*256, shv+3*256, 64, 1.0/M1);
    gemm_tc_kernel<<<dim3(2, M1/256),256,0,s1>>>(w[4], A1, B1, 64, 128, M1, scv+3*256, shv+3*256, gsum+4*256, gsq+4*256);
    finalize_kernel<<<1,256,0,s1>>>(gsum+4*256, gsq+4*256, g[4], bb[4], scv+4*256, shv+4*256, 128, 1.0/M1);
    gemm_tc_pool_kernel<<<dim3(4, M1/256),256,0,s1>>>(w[5], B1, 128, 256, M1, NS1, scv+4*256, shv+4*256, gsum+5*256, gsq+5*256, pmax1, pmin1);
    finalize_kernel<<<1,256,0,s1>>>(gsum+5*256, gsq+5*256, g[5], bb[5], scv+5*256, shv+5*256, 256, 1.0/M1);
    bn_pool_out_kernel<<<(256*NWIN)/256,256,0,s1>>>(pmax1, pmin1, scv+5*256, shv+5*256, outfeat, 256, 128);
    cudaEventRecord(evJ, s1);

    // ---- branch 0 (r=0.4, ns=32): 67 -> 64 -> 64 -> 128  [main stream] ----
    cudaStreamWaitEvent(0, evT, 0);
    gemm_g_kernel<<<dim3(1, M0/256),256,G_SMEM>>>(w[0], xyz, ft, newxyz, i0, A0, M0, NS0, gsum+0*256, gsq+0*256);
    finalize_kernel<<<1,256>>>(gsum+0*256, gsq+0*256, g[0], bb[0], scv+0*256, shv+0*256, 64, 1.0/M0);
    gemm_tc_kernel<<<dim3(1, M0/256),256>>>(w[1], A0, B0, 64, 64, M0, scv+0*256, shv+0*256, gsum+1*256, gsq+1*256);
    finalize_kernel<<<1,256>>>(gsum+1*256, gsq+1*256, g[1], bb[1], scv+1*256, shv+1*256, 64, 1.0/M0);
    gemm_tc_pool_kernel<<<dim3(2, M0/256),256>>>(w[2], B0, 64, 128, M0, NS0, scv+1*256, shv+1*256, gsum+2*256, gsq+2*256, pmax0, pmin0);
    finalize_kernel<<<1,256>>>(gsum+2*256, gsq+2*256, g[2], bb[2], scv+2*256, shv+2*256, 128, 1.0/M0);
    bn_pool_out_kernel<<<(128*NWIN)/256,256>>>(pmax0, pmin0, scv+2*256, shv+2*256, outfeat, 128, 0);

    // ---- join ----
    cudaStreamWaitEvent(0, evJ, 0);
}